// round 1
// baseline (speedup 1.0000x reference)
#include <cuda_runtime.h>
#include <math.h>

// Problem constants
#define BB   32
#define CC   256
#define HIN  30
#define OH   28
#define PPB  (OH*OH)        // 784 pixels per batch
#define NPIX (BB*PPB)       // 25088
#define NK   2048

// Pass-1 tiling
#define TILE_P 32
#define TILE_N 128
#define NTILES (NK/TILE_N)  // 16
#define THREADS 256
#define FSTR 260
#define ESTR 260
#define LSTR 33

// Pass-2
#define P2_K 8

// Scratch (static device arrays — no allocation)
__device__ float g_e2[NK];
__device__ float g_pixmax[NPIX];
__device__ float g_pixsum[NPIX];
__device__ float g_bow[BB*NK];

// ---------------------------------------------------------------------------
// Pass 0: e2[k] = sum_c embedding[k][c]^2   (one warp per code)
// ---------------------------------------------------------------------------
__global__ void e2_kernel(const float* __restrict__ emb) {
    int gw = blockIdx.x * (blockDim.x >> 5) + (threadIdx.x >> 5);
    int lane = threadIdx.x & 31;
    if (gw >= NK) return;
    const float4* row = reinterpret_cast<const float4*>(emb + (size_t)gw * CC);
    float s = 0.f;
    #pragma unroll
    for (int i = lane; i < CC/4; i += 32) {
        float4 v = row[i];
        s += v.x*v.x + v.y*v.y + v.z*v.z + v.w*v.w;
    }
    #pragma unroll
    for (int o = 16; o; o >>= 1) s += __shfl_xor_sync(0xffffffffu, s, o);
    if (lane == 0) g_e2[gw] = s;
}

// ---------------------------------------------------------------------------
// Pass 1: per 32-pixel block, GEMM vs all 2048 codes.
//   - writes raw logits (-alpha*dist) to the codes region of d_out
//   - maintains online softmax (running max + rescaled sum) per pixel
// smem layout (floats):
//   f_s   [32][260]  pixel-major features
//   e_s   [128][260] code-major embedding tile
//   lbuf  [128][33]  logit transpose buffer for coalesced stores
//   f2_s  [32], e2_s [128], red [256]
// ---------------------------------------------------------------------------
extern __shared__ float smem1[];

__global__ __launch_bounds__(THREADS, 1)
void pass1_kernel(const float* __restrict__ feat,
                  const float* __restrict__ emb,
                  const float* __restrict__ md,
                  float* __restrict__ out)
{
    float* f_s  = smem1;                     // 32*260   = 8320
    float* e_s  = f_s  + TILE_P*FSTR;        // 128*260  = 33280
    float* lbuf = e_s  + TILE_N*ESTR;        // 128*33   = 4224
    float* f2_s = lbuf + TILE_N*LSTR;        // 32
    float* e2_s = f2_s + TILE_P;             // 128
    float* red  = e2_s + TILE_N;             // 256

    const int tid = threadIdx.x;
    const int tx  = tid & 31;     // code lane
    const int ty  = tid >> 5;     // warp id -> pixel group
    const int gp0 = blockIdx.x * TILE_P;
    const float alpha = 15.0f / md[0];

    // ---- load feature tile + partial f2 ----
    float p2 = 0.f;
    {
        int i  = tid & 31;
        int gp = gp0 + i;
        int b  = gp / PPB;
        int r  = gp - b*PPB;
        int h  = r / OH, w = r - h*OH;
        int base = (b*CC*HIN + (h+1))*HIN + (w+1);
        for (int c = tid >> 5; c < CC; c += 8) {
            float v = feat[base + c*HIN*HIN];
            f_s[i*FSTR + c] = v;
            p2 += v*v;
        }
    }
    red[(tid >> 5)*32 + (tid & 31)] = p2;
    __syncthreads();
    if (tid < TILE_P) {
        float s = 0.f;
        #pragma unroll
        for (int j = 0; j < 8; j++) s += red[j*32 + tid];
        f2_s[tid] = s;
    }

    float mrun[4] = {-1e30f, -1e30f, -1e30f, -1e30f};
    float srun[4] = {0.f, 0.f, 0.f, 0.f};

    for (int nt = 0; nt < NTILES; ++nt) {
        __syncthreads();
        // ---- load embedding tile (coalesced float4, conflict-free stores) ----
        {
            const float4* eg = reinterpret_cast<const float4*>(emb + (size_t)nt*TILE_N*CC);
            for (int t = tid; t < TILE_N*CC/4; t += THREADS) {
                int code = t >> 6;          // /(CC/4)
                int c4   = t & 63;
                float4 v = eg[code*(CC/4) + c4];
                *reinterpret_cast<float4*>(&e_s[code*ESTR + c4*4]) = v;
            }
            if (tid < TILE_N) e2_s[tid] = g_e2[nt*TILE_N + tid];
        }
        __syncthreads();

        // ---- 32x128 GEMM, thread tile 4 pixels x 4 codes ----
        float acc[4][4];
        #pragma unroll
        for (int j = 0; j < 4; j++)
            #pragma unroll
            for (int m = 0; m < 4; m++) acc[j][m] = 0.f;

        #pragma unroll 2
        for (int kk = 0; kk < CC; kk += 4) {
            float4 fv[4], ev[4];
            #pragma unroll
            for (int j = 0; j < 4; j++)
                fv[j] = *reinterpret_cast<const float4*>(&f_s[(4*ty + j)*FSTR + kk]);
            #pragma unroll
            for (int m = 0; m < 4; m++)
                ev[m] = *reinterpret_cast<const float4*>(&e_s[(tx + 32*m)*ESTR + kk]);
            #pragma unroll
            for (int j = 0; j < 4; j++)
                #pragma unroll
                for (int m = 0; m < 4; m++) {
                    acc[j][m] += fv[j].x*ev[m].x;
                    acc[j][m] += fv[j].y*ev[m].y;
                    acc[j][m] += fv[j].z*ev[m].z;
                    acc[j][m] += fv[j].w*ev[m].w;
                }
        }

        // ---- epilogue: logits, online softmax, stage to lbuf ----
        #pragma unroll
        for (int j = 0; j < 4; j++) {
            float f2 = f2_s[4*ty + j];
            float l[4];
            float tmax = -1e30f;
            #pragma unroll
            for (int m = 0; m < 4; m++) {
                int cl = tx + 32*m;
                float dist = (f2 + e2_s[cl]) - 2.0f*acc[j][m];
                l[m] = -alpha * dist;
                lbuf[cl*LSTR + 4*ty + j] = l[m];
                tmax = fmaxf(tmax, l[m]);
            }
            #pragma unroll
            for (int o = 16; o; o >>= 1)
                tmax = fmaxf(tmax, __shfl_xor_sync(0xffffffffu, tmax, o));
            float mn = fmaxf(mrun[j], tmax);
            float se = 0.f;
            #pragma unroll
            for (int m = 0; m < 4; m++) se += __expf(l[m] - mn);
            #pragma unroll
            for (int o = 16; o; o >>= 1)
                se += __shfl_xor_sync(0xffffffffu, se, o);
            srun[j] = srun[j]*__expf(mrun[j] - mn) + se;
            mrun[j] = mn;
        }
        __syncthreads();

        // ---- coalesced logit store: codes[b][k][h][w] ----
        for (int t = tid; t < TILE_N*TILE_P; t += THREADS) {
            int cl = t >> 5;
            int i  = t & 31;
            int gp = gp0 + i;
            int b  = gp / PPB;
            int r  = gp - b*PPB;
            size_t addr = (size_t)(BB*NK)
                        + (((size_t)b*NK + (size_t)nt*TILE_N + cl)*PPB + r);
            out[addr] = lbuf[cl*LSTR + i];
        }
    }

    if (tx == 0) {
        #pragma unroll
        for (int j = 0; j < 4; j++) {
            int gp = gp0 + 4*ty + j;
            g_pixmax[gp] = mrun[j];
            g_pixsum[gp] = srun[j];
        }
    }
}

// ---------------------------------------------------------------------------
// Pass 2: codes = exp(l - m) / s  (in place), partial bow sums.
// One block per (b, 8 codes); m and 1/s staged in smem once per block.
// ---------------------------------------------------------------------------
__global__ __launch_bounds__(128)
void pass2_kernel(float* __restrict__ out) {
    __shared__ float4 sm_m[PPB/4], sm_s[PPB/4];
    __shared__ float redw[4];

    int b  = blockIdx.x / (NK / P2_K);
    int k0 = (blockIdx.x % (NK / P2_K)) * P2_K;
    int tid = threadIdx.x;

    const float* gm = g_pixmax + b*PPB;
    const float* gs = g_pixsum + b*PPB;
    for (int t = tid; t < PPB; t += 128) {
        reinterpret_cast<float*>(sm_m)[t] = gm[t];
        reinterpret_cast<float*>(sm_s)[t] = __frcp_rn(gs[t]);
    }
    __syncthreads();

    for (int kk = 0; kk < P2_K; kk++) {
        size_t base = (size_t)(BB*NK) + ((size_t)(b*NK + k0 + kk))*PPB;
        float4* p = reinterpret_cast<float4*>(out + base);
        float acc = 0.f;
        for (int t = tid; t < PPB/4; t += 128) {
            float4 v  = p[t];
            float4 m4 = sm_m[t];
            float4 s4 = sm_s[t];
            v.x = __expf(v.x - m4.x) * s4.x;
            v.y = __expf(v.y - m4.y) * s4.y;
            v.z = __expf(v.z - m4.z) * s4.z;
            v.w = __expf(v.w - m4.w) * s4.w;
            p[t] = v;
            acc += (v.x + v.y) + (v.z + v.w);
        }
        #pragma unroll
        for (int o = 16; o; o >>= 1) acc += __shfl_xor_sync(0xffffffffu, acc, o);
        if ((tid & 31) == 0) redw[tid >> 5] = acc;
        __syncthreads();
        if (tid == 0)
            g_bow[b*NK + k0 + kk] = (redw[0] + redw[1]) + (redw[2] + redw[3]);
        __syncthreads();
    }
}

// ---------------------------------------------------------------------------
// Pass 3: bow = mean / max(L1, eps), written to d_out[0 : B*NK]
// ---------------------------------------------------------------------------
__global__ __launch_bounds__(256)
void pass3_kernel(float* __restrict__ out) {
    __shared__ float redw[8];
    __shared__ float denom_s;
    int b   = blockIdx.x;
    int tid = threadIdx.x;
    const float invP = 1.0f / (float)PPB;

    float acc = 0.f;
    for (int k = tid; k < NK; k += 256) acc += g_bow[b*NK + k] * invP;
    #pragma unroll
    for (int o = 16; o; o >>= 1) acc += __shfl_xor_sync(0xffffffffu, acc, o);
    if ((tid & 31) == 0) redw[tid >> 5] = acc;
    __syncthreads();
    if (tid == 0) {
        float t = 0.f;
        #pragma unroll
        for (int i = 0; i < 8; i++) t += redw[i];
        denom_s = fmaxf(t, 1e-12f);
    }
    __syncthreads();
    float den = denom_s;
    for (int k = tid; k < NK; k += 256)
        out[b*NK + k] = (g_bow[b*NK + k] * invP) / den;
}

// ---------------------------------------------------------------------------
extern "C" void kernel_launch(void* const* d_in, const int* in_sizes, int n_in,
                              void* d_out, int out_size) {
    const float* feat = (const float*)d_in[0];   // (32,256,30,30)
    const float* emb  = (const float*)d_in[1];   // (2048,256)
    const float* md   = (const float*)d_in[2];   // (1,)
    float* out = (float*)d_out;                  // [bow 65536 | codes 51380224]

    const size_t SMEM1 = (size_t)(TILE_P*FSTR + TILE_N*ESTR + TILE_N*LSTR
                                  + TILE_P + TILE_N + 256) * sizeof(float);
    cudaFuncSetAttribute(pass1_kernel,
                         cudaFuncAttributeMaxDynamicSharedMemorySize, (int)SMEM1);

    e2_kernel  <<<NK/8, 256>>>(emb);
    pass1_kernel<<<NPIX/TILE_P, THREADS, SMEM1>>>(feat, emb, md, out);
    pass2_kernel<<<BB*NK/P2_K, 128>>>(out);
    pass3_kernel<<<BB, 256>>>(out);
    (void)in_sizes; (void)n_in; (void)out_size;
}

// round 2
// speedup vs baseline: 2.2457x; 2.2457x over previous
#include <cuda_runtime.h>
#include <cuda_fp16.h>
#include <math.h>

// Problem constants
#define BB   32
#define CC   256
#define HIN  30
#define OH   28
#define PPB  784
#define NPIX 25088
#define NK   2048
#define BOWOFF (BB*NK)

// Pass-1 tiling (tensor-core)
#define BM 64           // pixels per block
#define BN 256          // codes per tile
#define KC 64           // k-chunk (halves)
#define NTILE (NK/BN)   // 8
#define NSTAGE (NTILE*4*2) // 64 load stages (4 chunks x {hi,lo})
#define ASTR 272        // A smem row stride (halves): 136 words, mod32=8 -> conflict-free
#define BSTR 80         // B smem row stride (halves): 40 words,  mod32=8 -> conflict-free
#define LSTR2 66        // lbuf row stride (floats)

// smem byte offsets
#define OFF_AL   34816
#define OFF_B0   69632
#define OFF_B1   110592
#define OFF_LBUF 151552
#define OFF_MISC 219136
#define SMEM1_BYTES 221696

// Pass-2
#define P2_K 8

// Scratch
__device__ float g_e2[NK];
__device__ float g_pixmax[NPIX];
__device__ float g_pixsum[NPIX];
__device__ float g_bow[BB*NK];
__device__ __align__(16) __half g_ehiP[NK*CC];  // k-permuted fp16 hi split
__device__ __align__(16) __half g_eloP[NK*CC];  // k-permuted fp16 lo split

// ---------------------------------------------------------------------------
__device__ __forceinline__ void mma16816(float* c, const unsigned* a,
                                         unsigned b0, unsigned b1) {
    asm volatile(
        "mma.sync.aligned.m16n8k16.row.col.f32.f16.f16.f32 "
        "{%0,%1,%2,%3}, {%4,%5,%6,%7}, {%8,%9}, {%0,%1,%2,%3};"
        : "+f"(c[0]), "+f"(c[1]), "+f"(c[2]), "+f"(c[3])
        : "r"(a[0]), "r"(a[1]), "r"(a[2]), "r"(a[3]), "r"(b0), "r"(b1));
}

// ---------------------------------------------------------------------------
// Pass 0a: e2[k] = sum_c e[k][c]^2
// ---------------------------------------------------------------------------
__global__ void e2_kernel(const float* __restrict__ emb) {
    int gw = blockIdx.x * (blockDim.x >> 5) + (threadIdx.x >> 5);
    int lane = threadIdx.x & 31;
    if (gw >= NK) return;
    const float4* row = reinterpret_cast<const float4*>(emb + (size_t)gw * CC);
    float s = 0.f;
    #pragma unroll
    for (int i = lane; i < CC/4; i += 32) {
        float4 v = row[i];
        s += v.x*v.x + v.y*v.y + v.z*v.z + v.w*v.w;
    }
    #pragma unroll
    for (int o = 16; o; o >>= 1) s += __shfl_xor_sync(0xffffffffu, s, o);
    if (lane == 0) g_e2[gw] = s;
}

// ---------------------------------------------------------------------------
// Pass 0b: fp16 hi/lo split of embedding, written in k-interleaved order:
// within each 16-half k-group, pair j (k=2j,2j+1) goes to phys pair 2*(j&3)+(j>>2)
// so lane t's fragment halves {k=2(t%4)..+1, k+8..+9} are 4 contiguous halves.
// ---------------------------------------------------------------------------
__global__ void split_kernel(const float* __restrict__ emb) {
    int idx = blockIdx.x * 256 + threadIdx.x;     // over NK*CC/2 pairs
    if (idx >= NK*(CC/2)) return;
    int k  = idx >> 7;
    int cp = idx & 127;
    float v0 = emb[k*CC + 2*cp];
    float v1 = emb[k*CC + 2*cp + 1];
    __half h0 = __float2half_rn(v0), h1 = __float2half_rn(v1);
    __half l0 = __float2half_rn(v0 - __half2float(h0));
    __half l1 = __float2half_rn(v1 - __half2float(h1));
    int jp = cp & 7, grp = cp >> 3;
    int phys = grp*16 + (((jp & 3) << 1) + (jp >> 2)) * 2;
    *(__half2*)&g_ehiP[(size_t)k*CC + phys] = __halves2half2(h0, h1);
    *(__half2*)&g_eloP[(size_t)k*CC + phys] = __halves2half2(l0, l1);
}

// ---------------------------------------------------------------------------
// Pass 1: block = 64 pixels x all 2048 codes via fp16-split HMMA.
// 8 warps as 2m x 4n; warp tile 32m x 64n; acc fp32 [2][8][4].
// B (embedding splits) streamed via cp.async double buffer (64 stages).
// Per 256-code tile: logits -> lbuf -> online softmax -> coalesced gmem store.
// ---------------------------------------------------------------------------
__global__ __launch_bounds__(256, 1)
void pass1_kernel(const float* __restrict__ feat,
                  const float* __restrict__ md,
                  float* __restrict__ out)
{
    extern __shared__ char smem_raw[];
    __half* Ah    = (__half*)smem_raw;               // [64][272]
    __half* Al    = (__half*)(smem_raw + OFF_AL);    // [64][272]
    __half* Bb0   = (__half*)(smem_raw + OFF_B0);    // [256][80]
    __half* Bb1   = (__half*)(smem_raw + OFF_B1);    // [256][80]
    float*  lbuf  = (float*)(smem_raw + OFF_LBUF);   // [256][66]
    float*  f2s   = (float*)(smem_raw + OFF_MISC);   // 64  (-alpha*f2)
    float*  e2s   = f2s + 64;                        // 256 (-alpha*e2)
    float*  mnew  = e2s + 256;                       // 64
    float*  red   = mnew + 64;                       // 256

    const int tid  = threadIdx.x;
    const int warp = tid >> 5;
    const int lane = tid & 31;
    const int wm = warp >> 2;        // 0..1
    const int wn = warp & 3;         // 0..3
    const int tq = lane >> 2;        // 0..7
    const int tr = lane & 3;         // 0..3
    const int gp0 = blockIdx.x * BM;
    const float alpha  = 15.0f / md[0];
    const float alpha2 = 2.0f * alpha;

    // ---- issue helper: one B split-chunk (32 KB) via cp.async ----
    auto issue = [&](int s) {
        int tile = s >> 3, sub = s & 7;
        int chunk = sub >> 1, split = sub & 1;
        const __half* src = (split ? g_eloP : g_ehiP)
                          + (size_t)tile*BN*CC + chunk*KC;
        __half* dstB = (s & 1) ? Bb1 : Bb0;
        #pragma unroll
        for (int it = 0; it < 8; ++it) {
            int lin = it*256 + tid;
            int row = lin >> 3, seg = lin & 7;
            const __half* sp = src + row*CC + seg*8;
            unsigned d = (unsigned)__cvta_generic_to_shared(dstB + row*BSTR + seg*8);
            asm volatile("cp.async.cg.shared.global [%0], [%1], 16;"
                         :: "r"(d), "l"(sp) : "memory");
        }
        asm volatile("cp.async.commit_group;" ::: "memory");
    };

    issue(0);   // prefetch first B chunk ASAP

    // ---- load + split features, accumulate f2 ----
    {
        int p  = tid & 63;
        int q4 = tid >> 6;
        int gp = gp0 + p;
        int b  = gp / PPB;
        int r  = gp - b*PPB;
        int h  = r / OH, w = r - h*OH;
        const float* fb = feat + (size_t)b*CC*HIN*HIN + (h+1)*HIN + (w+1);
        float p2 = 0.f;
        for (int cp = q4; cp < 128; cp += 4) {
            float v0 = fb[(2*cp)*HIN*HIN];
            float v1 = fb[(2*cp+1)*HIN*HIN];
            p2 += v0*v0 + v1*v1;
            __half h0 = __float2half_rn(v0), h1 = __float2half_rn(v1);
            __half l0 = __float2half_rn(v0 - __half2float(h0));
            __half l1 = __float2half_rn(v1 - __half2float(h1));
            int jp = cp & 7, grp = cp >> 3;
            int phys = grp*16 + (((jp & 3) << 1) + (jp >> 2)) * 2;
            *(__half2*)&Ah[p*ASTR + phys] = __halves2half2(h0, h1);
            *(__half2*)&Al[p*ASTR + phys] = __halves2half2(l0, l1);
        }
        red[q4*64 + p] = p2;
    }
    __syncthreads();
    if (tid < 64)
        f2s[tid] = -alpha * (red[tid] + red[64+tid] + red[128+tid] + red[192+tid]);

    float m_run = -1e30f, s_run = 0.f;
    float acc[2][8][4];

    for (int s = 0; s < NSTAGE; ++s) {
        const int tile  = s >> 3;
        const int sub   = s & 7;
        const int chunk = sub >> 1;
        const int split = sub & 1;
        const __half* B = (s & 1) ? Bb1 : Bb0;

        asm volatile("cp.async.wait_group 0;" ::: "memory");
        __syncthreads();

        if (sub == 0) {
            #pragma unroll
            for (int mt = 0; mt < 2; ++mt)
                #pragma unroll
                for (int nt = 0; nt < 8; ++nt)
                    #pragma unroll
                    for (int i = 0; i < 4; ++i) acc[mt][nt][i] = 0.f;
            e2s[tid] = -alpha * g_e2[tile*BN + tid];
        }
        if (s + 1 < NSTAGE) issue(s + 1);

        // ---- mma: split==0 -> (Ah,Bhi)+(Al,Bhi); split==1 -> (Ah,Blo) ----
        const int kc = chunk * KC;
        const int npass = (split == 0) ? 2 : 1;
        for (int pass = 0; pass < npass; ++pass) {
            const __half* Ap = (pass == 1) ? Al : Ah;
            #pragma unroll
            for (int g = 0; g < 4; ++g) {
                unsigned afr[2][4];
                #pragma unroll
                for (int mt = 0; mt < 2; ++mt) {
                    int row = wm*32 + mt*16 + tq;
                    uint2 x = *(const uint2*)&Ap[row*ASTR + kc + g*16 + 4*tr];
                    uint2 y = *(const uint2*)&Ap[(row+8)*ASTR + kc + g*16 + 4*tr];
                    afr[mt][0] = x.x; afr[mt][1] = y.x;
                    afr[mt][2] = x.y; afr[mt][3] = y.y;
                }
                #pragma unroll
                for (int nt = 0; nt < 8; ++nt) {
                    int brow = wn*64 + nt*8 + tq;
                    uint2 z = *(const uint2*)&B[brow*BSTR + g*16 + 4*tr];
                    mma16816(acc[0][nt], afr[0], z.x, z.y);
                    mma16816(acc[1][nt], afr[1], z.x, z.y);
                }
            }
        }

        if (sub == 7) {
            // ---- stage logits to lbuf[n][m] ----
            #pragma unroll
            for (int mt = 0; mt < 2; ++mt) {
                int m0 = wm*32 + mt*16 + tq;
                float c1a = f2s[m0], c1b = f2s[m0+8];
                #pragma unroll
                for (int nt = 0; nt < 8; ++nt) {
                    int n0 = wn*64 + nt*8 + 2*tr;
                    float e0 = e2s[n0], e1 = e2s[n0+1];
                    lbuf[n0*LSTR2 + m0]       = fmaf(alpha2, acc[mt][nt][0], c1a + e0);
                    lbuf[(n0+1)*LSTR2 + m0]   = fmaf(alpha2, acc[mt][nt][1], c1a + e1);
                    lbuf[n0*LSTR2 + m0+8]     = fmaf(alpha2, acc[mt][nt][2], c1b + e0);
                    lbuf[(n0+1)*LSTR2 + m0+8] = fmaf(alpha2, acc[mt][nt][3], c1b + e1);
                }
            }
            __syncthreads();

            // ---- per-pixel online softmax over this tile's 256 codes ----
            const int p = tid & 63, q = tid >> 6;
            float mloc = -1e30f;
            #pragma unroll 8
            for (int i = 0; i < 64; ++i)
                mloc = fmaxf(mloc, lbuf[(q + 4*i)*LSTR2 + p]);
            red[q*64 + p] = mloc;
            __syncthreads();
            if (q == 0) {
                float mm = fmaxf(fmaxf(red[p], red[64+p]),
                                 fmaxf(red[128+p], red[192+p]));
                mnew[p] = fmaxf(mm, m_run);
            }
            __syncthreads();
            float mn = mnew[p];
            float sloc = 0.f;
            #pragma unroll 8
            for (int i = 0; i < 64; ++i)
                sloc += __expf(lbuf[(q + 4*i)*LSTR2 + p] - mn);
            red[q*64 + p] = sloc;
            __syncthreads();
            if (q == 0) {
                float ss = red[p] + red[64+p] + red[128+p] + red[192+p];
                s_run = s_run * __expf(m_run - mn) + ss;
                m_run = mn;
            }

            // ---- coalesced logit store: codes[b][k][h][w] ----
            for (int t2 = tid; t2 < BN*BM; t2 += 256) {
                int n = t2 >> 6, mm = t2 & 63;
                int gp = gp0 + mm;
                int b  = gp / PPB, r = gp - b*PPB;
                out[BOWOFF + ((size_t)(b*NK + tile*BN + n))*PPB + r] =
                    lbuf[n*LSTR2 + mm];
            }
            __syncthreads();   // protect lbuf before next tile's staging
        }
    }

    if (tid < 64) {
        g_pixmax[gp0 + tid] = m_run;
        g_pixsum[gp0 + tid] = s_run;
    }
}

// ---------------------------------------------------------------------------
// Pass 2: codes = exp(l - m) / s (in place), partial bow sums.
// ---------------------------------------------------------------------------
__global__ __launch_bounds__(128)
void pass2_kernel(float* __restrict__ out) {
    __shared__ float4 sm_m[PPB/4], sm_s[PPB/4];
    __shared__ float redw[4];

    int b  = blockIdx.x / (NK / P2_K);
    int k0 = (blockIdx.x % (NK / P2_K)) * P2_K;
    int tid = threadIdx.x;

    const float* gm = g_pixmax + b*PPB;
    const float* gs = g_pixsum + b*PPB;
    for (int t = tid; t < PPB; t += 128) {
        reinterpret_cast<float*>(sm_m)[t] = gm[t];
        reinterpret_cast<float*>(sm_s)[t] = __frcp_rn(gs[t]);
    }
    __syncthreads();

    for (int kk = 0; kk < P2_K; kk++) {
        size_t base = (size_t)BOWOFF + ((size_t)(b*NK + k0 + kk))*PPB;
        float4* p = reinterpret_cast<float4*>(out + base);
        float acc = 0.f;
        for (int t = tid; t < PPB/4; t += 128) {
            float4 v  = p[t];
            float4 m4 = sm_m[t];
            float4 s4 = sm_s[t];
            v.x = __expf(v.x - m4.x) * s4.x;
            v.y = __expf(v.y - m4.y) * s4.y;
            v.z = __expf(v.z - m4.z) * s4.z;
            v.w = __expf(v.w - m4.w) * s4.w;
            p[t] = v;
            acc += (v.x + v.y) + (v.z + v.w);
        }
        #pragma unroll
        for (int o = 16; o; o >>= 1) acc += __shfl_xor_sync(0xffffffffu, acc, o);
        if ((tid & 31) == 0) redw[tid >> 5] = acc;
        __syncthreads();
        if (tid == 0)
            g_bow[b*NK + k0 + kk] = (redw[0] + redw[1]) + (redw[2] + redw[3]);
        __syncthreads();
    }
}

// ---------------------------------------------------------------------------
// Pass 3: bow normalize
// ---------------------------------------------------------------------------
__global__ __launch_bounds__(256)
void pass3_kernel(float* __restrict__ out) {
    __shared__ float redw[8];
    __shared__ float denom_s;
    int b   = blockIdx.x;
    int tid = threadIdx.x;
    const float invP = 1.0f / (float)PPB;

    float acc = 0.f;
    for (int k = tid; k < NK; k += 256) acc += g_bow[b*NK + k] * invP;
    #pragma unroll
    for (int o = 16; o; o >>= 1) acc += __shfl_xor_sync(0xffffffffu, acc, o);
    if ((tid & 31) == 0) redw[tid >> 5] = acc;
    __syncthreads();
    if (tid == 0) {
        float t = 0.f;
        #pragma unroll
        for (int i = 0; i < 8; i++) t += redw[i];
        denom_s = fmaxf(t, 1e-12f);
    }
    __syncthreads();
    float den = denom_s;
    for (int k = tid; k < NK; k += 256)
        out[b*NK + k] = (g_bow[b*NK + k] * invP) / den;
}

// ---------------------------------------------------------------------------
extern "C" void kernel_launch(void* const* d_in, const int* in_sizes, int n_in,
                              void* d_out, int out_size) {
    const float* feat = (const float*)d_in[0];   // (32,256,30,30)
    const float* emb  = (const float*)d_in[1];   // (2048,256)
    const float* md   = (const float*)d_in[2];   // (1,)
    float* out = (float*)d_out;

    cudaFuncSetAttribute(pass1_kernel,
                         cudaFuncAttributeMaxDynamicSharedMemorySize, SMEM1_BYTES);

    e2_kernel   <<<NK/8, 256>>>(emb);
    split_kernel<<<NK*CC/2/256, 256>>>(emb);
    pass1_kernel<<<NPIX/BM, 256, SMEM1_BYTES>>>(feat, md, out);
    pass2_kernel<<<BB*NK/P2_K, 128>>>(out);
    pass3_kernel<<<BB, 256>>>(out);
    (void)in_sizes; (void)n_in; (void)out_size;
}